// round 6
// baseline (speedup 1.0000x reference)
#include <cuda_runtime.h>
#include <stdint.h>

// PatchMasker: out = concat(where(mask[t],0,x_dist), where(mask[t],0,x_tre),
//                           where(mask[t],0,x_sea))
// x_* = (B=256, T=512, F=256) fp32, mask = (T=512,) int32.
// HBM/LTS-capped streaming kernel (measured cap ~6.3 TB/s, path-independent).
// Masked rows skip the input read (predicated LDG) -> traffic is minimal:
// 403 MB writes + ~184 MB reads.
//
// R5 -> R6: persistent grid-stride. 768 resident CTAs (no wave transitions,
// no per-CTA launch/drain ramp), each running exactly 32 unroll-4 iterations
// over warp-contiguous stripes. All index math is shifts (N4_PER = 2^23).

#define B_DIM 256
#define T_DIM 512
#define F_DIM 256

#define N4_PER   ((long)B_DIM * T_DIM * F_DIM / 4)  // 2^23 float4 per tensor
#define TENSOR_SHIFT 23                             // i >> 23 = tensor id
#define N4_MASK  (N4_PER - 1)
#define ROW_SHIFT 6                                 // 64 float4 per (b,t) row
#define T_MASK   (T_DIM - 1)

#define BLK      256
#define NBLOCKS  768                 // all resident (~5.2 CTA/SM), 1 wave
#define GSTRIDE  ((long)NBLOCKS * BLK)      // 196608
#define UNROLL   4
#define NITER    32                  // 3*2^23 / (GSTRIDE*UNROLL) == 32 exact

__global__ void __launch_bounds__(BLK, 8)
patch_masker_kernel(const float4* __restrict__ xd,
                    const float4* __restrict__ xt,
                    const float4* __restrict__ xs,
                    const int* __restrict__ mask,
                    float4* __restrict__ out)
{
    const float4* srcs[3] = { xd, xt, xs };
    long i0 = (long)blockIdx.x * BLK + threadIdx.x;

    const float4 z = make_float4(0.f, 0.f, 0.f, 0.f);

    for (int it = 0; it < NITER; it++) {
        long ibase = i0 + (long)it * (GSTRIDE * UNROLL);

        long  idx[UNROLL];
        const float4* src[UNROLL];
        long  rem[UNROLL];
        bool  k[UNROLL];
        float4 v[UNROLL];

#pragma unroll
        for (int j = 0; j < UNROLL; j++) {
            idx[j] = ibase + (long)j * GSTRIDE;        // warp-contiguous
            int tensor = (int)(idx[j] >> TENSOR_SHIFT);
            rem[j] = idx[j] & N4_MASK;
            src[j] = srcs[tensor];
            int t = (int)((rem[j] >> ROW_SHIFT) & T_MASK);
            k[j] = (mask[t] == 0);                     // 2 KB, L1-resident
            v[j] = z;
        }

        // Front-batched independent predicated loads (4 LDG.128 in flight).
#pragma unroll
        for (int j = 0; j < UNROLL; j++) {
            if (k[j]) v[j] = __ldcs(&src[j][rem[j]]);
        }

#pragma unroll
        for (int j = 0; j < UNROLL; j++) {
            __stcs(&out[idx[j]], v[j]);
        }
    }
}

extern "C" void kernel_launch(void* const* d_in, const int* in_sizes, int n_in,
                              void* d_out, int out_size)
{
    const float4* xd = (const float4*)d_in[0];
    const float4* xt = (const float4*)d_in[1];
    const float4* xs = (const float4*)d_in[2];
    const int* mask  = (const int*)d_in[3];
    float4* out = (float4*)d_out;

    patch_masker_kernel<<<NBLOCKS, BLK>>>(xd, xt, xs, mask, out);
}

// round 7
// speedup vs baseline: 1.1509x; 1.1509x over previous
#include <cuda_runtime.h>
#include <stdint.h>

// PatchMasker: out = concat(where(mask[t], 0, x_dist),
//                           where(mask[t], 0, x_tre),
//                           where(mask[t], 0, x_sea))
// x_* = (B=256, T=512, F=256) fp32, mask = (T=512,) int32.
//
// FINAL (converged): pure HBM-streaming kernel pinned at the B300 chip-level
// LTS throughput cap (~6300 GB/s, path-independent per HW measurement).
// Traffic is information-theoretically minimal: all 403 MB of output written,
// input reads predicated off for masked rows (~40% of T), ~587 MB total.
// Three structurally different designs (R2/R4/R5) all measured 93.2-93.5 us
// at DRAM=79.5%; persistent-CTA variant regressed. One tensor per blockIdx.y
// (1 read + 1 write stream per block), 4 warp-coalesced float4 per thread.

#define B_DIM 256
#define T_DIM 512
#define F_DIM 256

#define N4_PER ((long)B_DIM * T_DIM * F_DIM / 4)  // float4 per tensor = 2^23
#define ROW_SHIFT 6                               // 64 float4 per (b,t) row
#define T_MASK (T_DIM - 1)
#define BLK 256
#define F4_PER_THREAD 4
#define F4_PER_BLOCK (F4_PER_THREAD * BLK)        // 1024

__global__ void __launch_bounds__(BLK, 8)
patch_masker_kernel(const float4* __restrict__ xd,
                    const float4* __restrict__ xt,
                    const float4* __restrict__ xs,
                    const int* __restrict__ mask,
                    float4* __restrict__ out)
{
    // One tensor per blockIdx.y: exactly 1 read + 1 write stream per block.
    const float4* __restrict__ src =
        (blockIdx.y == 0) ? xd : (blockIdx.y == 1) ? xt : xs;
    float4* __restrict__ dst = out + (long)blockIdx.y * N4_PER;

    long base = (long)blockIdx.x * F4_PER_BLOCK + threadIdx.x;

    const float4 z = make_float4(0.f, 0.f, 0.f, 0.f);
    float4 v[F4_PER_THREAD];
    bool  k[F4_PER_THREAD];
    long  idx[F4_PER_THREAD];

#pragma unroll
    for (int j = 0; j < F4_PER_THREAD; j++) {
        idx[j] = base + (long)j * BLK;               // warp-contiguous
        int t = (int)((idx[j] >> ROW_SHIFT) & T_MASK);
        k[j] = (mask[t] == 0);                       // 2 KB table, L1-resident
        v[j] = z;
    }

    // Front-batched independent predicated loads (up to 4 LDG.128 in flight);
    // masked rows generate zero read traffic.
#pragma unroll
    for (int j = 0; j < F4_PER_THREAD; j++) {
        if (k[j]) v[j] = __ldcs(&src[idx[j]]);
    }

#pragma unroll
    for (int j = 0; j < F4_PER_THREAD; j++) {
        __stcs(&dst[idx[j]], v[j]);
    }
}

extern "C" void kernel_launch(void* const* d_in, const int* in_sizes, int n_in,
                              void* d_out, int out_size)
{
    const float4* xd = (const float4*)d_in[0];
    const float4* xt = (const float4*)d_in[1];
    const float4* xs = (const float4*)d_in[2];
    const int* mask  = (const int*)d_in[3];
    float4* out = (float4*)d_out;

    dim3 grid((unsigned)(N4_PER / F4_PER_BLOCK), 3);  // (8192, 3), exact
    patch_masker_kernel<<<grid, BLK>>>(xd, xt, xs, mask, out);
}